// round 16
// baseline (speedup 1.0000x reference)
#include <cuda_runtime.h>
#include <cuda_bf16.h>

#define Hh  8
#define Dd  256
#define HDe 32
#define Bb  16
#define Qq  512
#define S1c 64
#define Tt  448

typedef unsigned long long u64;
typedef unsigned int u32;
typedef __nv_bfloat16  bf16;
typedef __nv_bfloat162 bf162;

// ---------------- static scratch ----------------
__device__ float g_P1[128*Tt*Tt];
__device__ float g_P2[128*Tt*S1c];
__device__ float g_P3[128*S1c*Tt];

__device__ bf16 g_Xhi[Bb*Qq*Dd], g_Xlo[Bb*Qq*Dd];
__device__ bf16 g_Hhi[Bb*Qq*Dd], g_Hlo[Bb*Qq*Dd];
__device__ bf16 g_Wbh[8*256*256], g_Wbl[8*256*256];

__device__ bf16 g_Q1h[128*Tt*32],  g_Q1l[128*Tt*32];
__device__ bf16 g_Q0h[128*Tt*32],  g_Q0l[128*Tt*32];
__device__ bf16 g_Kch[128*Tt*32],  g_Kcl[128*Tt*32];
__device__ bf16 g_Vch[128*Tt*32],  g_Vcl[128*Tt*32];
__device__ bf16 g_Qsh[128*S1c*32], g_Qsl[128*S1c*32];
__device__ bf16 g_Ksh[128*S1c*32], g_Ksl[128*S1c*32];
__device__ bf16 g_Vsh[128*S1c*32], g_Vsl[128*S1c*32];

__device__ bf16 g_P1h[128*Tt*Tt],  g_P1l[128*Tt*Tt];
__device__ bf16 g_P2h[128*Tt*S1c], g_P2l[128*Tt*S1c];
__device__ bf16 g_P3h[128*S1c*Tt], g_P3l[128*S1c*Tt];

// ================= conversion kernels =================
__global__ __launch_bounds__(256) void cvt_split_kernel(
    const float* __restrict__ src, bf16* __restrict__ hi,
    bf16* __restrict__ lo, int n4)
{
    int i = blockIdx.x * 256 + threadIdx.x;
    if (i >= n4) return;
    float4 v = ((const float4*)src)[i];
    bf16 h0 = __float2bfloat16(v.x), h1 = __float2bfloat16(v.y);
    bf16 h2 = __float2bfloat16(v.z), h3 = __float2bfloat16(v.w);
    ((bf162*)hi)[i*2]   = bf162(h0, h1);
    ((bf162*)hi)[i*2+1] = bf162(h2, h3);
    ((bf162*)lo)[i*2]   = bf162(__float2bfloat16(v.x - __bfloat162float(h0)),
                                __float2bfloat16(v.y - __bfloat162float(h1)));
    ((bf162*)lo)[i*2+1] = bf162(__float2bfloat16(v.z - __bfloat162float(h2)),
                                __float2bfloat16(v.w - __bfloat162float(h3)));
}

struct WArgs { const float* W[8]; };

__global__ __launch_bounds__(256) void cvt_w_kernel(
    WArgs wa, bf16* __restrict__ bh, bf16* __restrict__ bl)
{
    int i = blockIdx.x * 256 + threadIdx.x;
    int s = i >> 16;
    int r = i & 65535;
    int c = r >> 8, k = r & 255;
    const float* W = wa.W[s];
    float x = (s < 7) ? W[(c >> 5) * 8192 + k * 32 + (c & 31)] : W[k * 256 + c];
    bf16 h = __float2bfloat16(x);
    bh[i] = h;
    bl[i] = __float2bfloat16(x - __bfloat162float(h));
}

// ================= shared HMMA machinery =================
#define ASTR 40

__device__ __forceinline__ u32 smaddr(const void* p) {
    return (u32)__cvta_generic_to_shared(p);
}
__device__ __forceinline__ void ldsm4(u32& r0, u32& r1, u32& r2, u32& r3, u32 a) {
    asm volatile("ldmatrix.sync.aligned.m8n8.x4.shared.b16 {%0,%1,%2,%3},[%4];"
        : "=r"(r0), "=r"(r1), "=r"(r2), "=r"(r3) : "r"(a));
}
__device__ __forceinline__ void ldsm4t(u32& r0, u32& r1, u32& r2, u32& r3, u32 a) {
    asm volatile("ldmatrix.sync.aligned.m8n8.x4.trans.shared.b16 {%0,%1,%2,%3},[%4];"
        : "=r"(r0), "=r"(r1), "=r"(r2), "=r"(r3) : "r"(a));
}

__device__ __forceinline__ void ldA(u32* a, const bf16 (*M)[ASTR], int R0, int ks, int lane) {
    int row = R0 + ((lane >> 3) & 1) * 8 + (lane & 7);
    int kg  = 2 * ks + (lane >> 4);
    ldsm4(a[0], a[1], a[2], a[3], smaddr(&M[row][((kg + (row >> 3)) & 3) << 3]));
}
__device__ __forceinline__ void ldB(u32* b, const bf16 (*M)[ASTR], int N0, int ks, int lane) {
    int row = N0 + (lane >> 4) * 8 + (lane & 7);
    int kg  = 2 * ks + ((lane >> 3) & 1);
    ldsm4(b[0], b[1], b[2], b[3], smaddr(&M[row][((kg + (row >> 3)) & 3) << 3]));
}
__device__ __forceinline__ void ldBt(u32* b, const bf16 (*M)[ASTR], int nfp, int ks, int lane) {
    int row = ks * 16 + ((lane >> 3) & 1) * 8 + (lane & 7);
    int eg  = nfp * 2 + (lane >> 4);
    ldsm4t(b[0], b[1], b[2], b[3], smaddr(&M[row][((eg + (row >> 3)) & 3) << 3]));
}

__device__ __forceinline__ void mma_bf16(float* d, const u32* a, u32 b0, u32 b1) {
    asm volatile(
        "mma.sync.aligned.m16n8k16.row.col.f32.bf16.bf16.f32 "
        "{%0,%1,%2,%3}, {%4,%5,%6,%7}, {%8,%9}, {%0,%1,%2,%3};"
        : "+f"(d[0]), "+f"(d[1]), "+f"(d[2]), "+f"(d[3])
        : "r"(a[0]), "r"(a[1]), "r"(a[2]), "r"(a[3]), "r"(b0), "r"(b1));
}

__device__ __forceinline__ void split_st(bf16* hp, bf16* lp, size_t idx, float2 v) {
    bf16 h0 = __float2bfloat16(v.x), h1 = __float2bfloat16(v.y);
    *(bf162*)(hp + idx) = bf162(h0, h1);
    *(bf162*)(lp + idx) = bf162(__float2bfloat16(v.x - __bfloat162float(h0)),
                                __float2bfloat16(v.y - __bfloat162float(h1)));
}

// pack two fp32 into bf16x2 {lo=x, hi=y} plus residual pair
__device__ __forceinline__ void split2(float x, float y, u32& hi, u32& lo) {
    float xh = __bfloat162float(__float2bfloat16(x));
    float yh = __bfloat162float(__float2bfloat16(y));
    asm("cvt.rn.bf16x2.f32 %0, %1, %2;" : "=r"(hi) : "f"(yh), "f"(xh));
    asm("cvt.rn.bf16x2.f32 %0, %1, %2;" : "=r"(lo) : "f"(y - yh), "f"(x - xh));
}

// fill one 64-row tile (hi or lo selected by sel) from [(rowbase+rr)*32] source
__device__ __forceinline__ void fill_tile(
    bf16 (*Dh)[ASTR], bf16 (*Dl)[ASTR],
    const bf16* __restrict__ srcH, const bf16* __restrict__ srcL,
    size_t rowbase, int rr, int sel, int rsw)
{
    const uint4* s = (const uint4*)((sel ? srcL : srcH) + (rowbase + rr) * 32);
    bf16 (*D)[ASTR] = sel ? Dl : Dh;
#pragma unroll
    for (int g = 0; g < 4; g++) {
        int pg = ((g + rsw) & 3) << 3;
        *(uint4*)&D[rr][pg] = s[g];
    }
}

// ================= proj/out HMMA kernel =================
struct HArgs {
    const bf16 *Ahi, *Alo;
    const bf16 *Bh, *Bl;
    float* Ofp;
    bf16 *Oh[7], *Ol[7];
    int mode;
};

__global__ __launch_bounds__(128) void hmma_kernel(HArgs args)
{
    __shared__ __align__(16) bf16 Ah[128][ASTR], Al[128][ASTR];
    __shared__ __align__(16) bf16 Bhs[64][ASTR], Bls[64][ASTR];
    const int x = blockIdx.x, y = blockIdx.y;
    int set, col0, TL, qoff, m0;
    if (args.mode == 0) {
        if (x < 56) { set = y >> 2; col0 = (y & 3) * 64; TL = Tt; qoff = S1c; m0 = x * 128; }
        else {
            if (y >= 12) return;
            set = 4 + (y >> 2); col0 = (y & 3) * 64; TL = S1c; qoff = 0; m0 = (x - 56) * 128;
        }
    } else { set = 7; col0 = y * 64; TL = Qq; qoff = 0; m0 = x * 128; }

    const int tid = threadIdx.x;
    const int warp = tid >> 5, lane = tid & 31;

    float acc[2][8][4];
#pragma unroll
    for (int mf = 0; mf < 2; mf++)
#pragma unroll
        for (int nf = 0; nf < 8; nf++)
#pragma unroll
            for (int j = 0; j < 4; j++) acc[mf][nf][j] = 0.f;

    int t = m0 + tid;
    int ab = t / TL;
    size_t arow = ((size_t)ab * Qq + qoff + (t - ab * TL)) * 256;
    const int br = tid & 63;
    const bf16* Bsrc = ((tid < 64) ? args.Bh : args.Bl) + (size_t)set * 65536 + (size_t)(col0 + br) * 256;
    const int rswA = (tid >> 3) & 3;
    const int rswB = (br >> 3) & 3;

    for (int k0 = 0; k0 < 256; k0 += 32) {
        if (k0) __syncthreads();
        const uint4* sAh = (const uint4*)(args.Ahi + arow + k0);
        const uint4* sAl = (const uint4*)(args.Alo + arow + k0);
#pragma unroll
        for (int g = 0; g < 4; g++) {
            int pg = ((g + rswA) & 3) << 3;
            *(uint4*)&Ah[tid][pg] = sAh[g];
            *(uint4*)&Al[tid][pg] = sAl[g];
        }
        {
            const uint4* sB = (const uint4*)(Bsrc + k0);
            bf16 (*Bd)[ASTR] = (tid < 64) ? Bhs : Bls;
#pragma unroll
            for (int g = 0; g < 4; g++) {
                int pg = ((g + rswB) & 3) << 3;
                *(uint4*)&Bd[br][pg] = sB[g];
            }
        }
        __syncthreads();
#pragma unroll
        for (int ks = 0; ks < 2; ks++) {
            u32 ah[2][4], al[2][4];
            ldA(ah[0], Ah, warp * 32,      ks, lane);
            ldA(ah[1], Ah, warp * 32 + 16, ks, lane);
            ldA(al[0], Al, warp * 32,      ks, lane);
            ldA(al[1], Al, warp * 32 + 16, ks, lane);
#pragma unroll
            for (int np = 0; np < 4; np++) {
                u32 bh[4], bl[4];
                ldB(bh, Bhs, np * 16, ks, lane);
                ldB(bl, Bls, np * 16, ks, lane);
#pragma unroll
                for (int q = 0; q < 2; q++) {
                    int nf = np * 2 + q;
#pragma unroll
                    for (int mf = 0; mf < 2; mf++) {
                        mma_bf16(acc[mf][nf], ah[mf], bh[2*q], bh[2*q+1]);
                        mma_bf16(acc[mf][nf], ah[mf], bl[2*q], bl[2*q+1]);
                        mma_bf16(acc[mf][nf], al[mf], bh[2*q], bh[2*q+1]);
                    }
                }
            }
        }
    }

#pragma unroll
    for (int mf = 0; mf < 2; mf++) {
#pragma unroll
        for (int nf = 0; nf < 8; nf++) {
            int lc = nf * 8 + (lane & 3) * 2;
            int t0 = m0 + warp * 32 + mf * 16 + (lane >> 2);
            int t1 = t0 + 8;
            float2 v0 = make_float2(acc[mf][nf][0], acc[mf][nf][1]);
            float2 v1 = make_float2(acc[mf][nf][2], acc[mf][nf][3]);
            if (args.mode == 0) {
                int c = col0 + lc;
                int h = c >> 5, e = c & 31;
                int b0i = t0 / TL, n0i = t0 - b0i * TL;
                int b1i = t1 / TL, n1i = t1 - b1i * TL;
                size_t i0 = (((size_t)h * Bb + b0i) * TL + n0i) * 32 + e;
                size_t i1 = (((size_t)h * Bb + b1i) * TL + n1i) * 32 + e;
                split_st(args.Oh[set], args.Ol[set], i0, v0);
                split_st(args.Oh[set], args.Ol[set], i1, v1);
            } else {
                int d = col0 + lc;
                *(float2*)(args.Ofp + (size_t)t0 * 256 + d) = v0;
                *(float2*)(args.Ofp + (size_t)t1 * 256 + d) = v1;
            }
        }
    }
}

// ================= QK^T HMMA (stationary tile + double-buffered stream) =========
struct QKArgs {
    const bf16 *Q1h, *Q1l, *Q0h, *Q0l, *Qsh, *Qsl;
    const bf16 *Kch, *Kcl, *Ksh, *Ksl;
    float *P1, *P2, *P3;
};

__device__ __forceinline__ void qk_tile(
    const bf16 (*Qhs)[ASTR], const bf16 (*Qls)[ASTR],
    const bf16 (*Khs)[ASTR], const bf16 (*Kls)[ASTR],
    float* Sb, int Nk, int row0, int col0, int warp, int lane)
{
    float acc[8][4];
#pragma unroll
    for (int nf = 0; nf < 8; nf++)
#pragma unroll
        for (int j = 0; j < 4; j++) acc[nf][j] = 0.f;
#pragma unroll
    for (int ks = 0; ks < 2; ks++) {
        u32 ah[4], al[4];
        ldA(ah, Qhs, warp * 16, ks, lane);
        ldA(al, Qls, warp * 16, ks, lane);
#pragma unroll
        for (int np = 0; np < 4; np++) {
            u32 bh[4], bl[4];
            ldB(bh, Khs, np * 16, ks, lane);
            ldB(bl, Kls, np * 16, ks, lane);
#pragma unroll
            for (int q = 0; q < 2; q++) {
                int nf = np * 2 + q;
                mma_bf16(acc[nf], ah, bh[2*q], bh[2*q+1]);
                mma_bf16(acc[nf], ah, bl[2*q], bl[2*q+1]);
                mma_bf16(acc[nf], al, bh[2*q], bh[2*q+1]);
            }
        }
    }
#pragma unroll
    for (int nf = 0; nf < 8; nf++) {
        int col = col0 + nf * 8 + (lane & 3) * 2;
        int r0 = row0 + warp * 16 + (lane >> 2);
        *(float2*)(Sb + (size_t)r0 * Nk + col)       = make_float2(acc[nf][0], acc[nf][1]);
        *(float2*)(Sb + (size_t)(r0 + 8) * Nk + col) = make_float2(acc[nf][2], acc[nf][3]);
    }
}

__global__ __launch_bounds__(128) void qk_hmma(QKArgs a)
{
    __shared__ __align__(16) bf16 Sth[64][ASTR], Stl[64][ASTR];        // stationary
    __shared__ __align__(16) bf16 Dbh[2][64][ASTR], Dbl[2][64][ASTR];  // streamed (dbl-buf)
    const int x = blockIdx.x, z = blockIdx.y;
    const int tid = threadIdx.x;
    const int warp = tid >> 5, lane = tid & 31;
    const int rr = tid & 63;
    const int sel = tid >> 6;
    const int rsw = (rr >> 3) & 3;

    if (x < 7) {
        // job1: stationary Q1 tile x, stream 7 Kc tiles
        fill_tile(Sth, Stl, a.Q1h, a.Q1l, (size_t)z * Tt + x * 64, rr, sel, rsw);
        fill_tile(Dbh[0], Dbl[0], a.Kch, a.Kcl, (size_t)z * Tt, rr, sel, rsw);
        __syncthreads();
        float* Sb = a.P1 + (size_t)z * Tt * Tt;
        for (int mt = 0; mt < 7; mt++) {
            if (mt < 6)
                fill_tile(Dbh[(mt+1)&1], Dbl[(mt+1)&1], a.Kch, a.Kcl,
                          (size_t)z * Tt + (mt+1) * 64, rr, sel, rsw);
            qk_tile(Sth, Stl, Dbh[mt&1], Dbl[mt&1], Sb, Tt, x * 64, mt * 64, warp, lane);
            __syncthreads();
        }
    } else if (x == 7) {
        // job2: stationary Ks, stream 7 Q0 tiles
        fill_tile(Sth, Stl, a.Ksh, a.Ksl, (size_t)z * S1c, rr, sel, rsw);
        fill_tile(Dbh[0], Dbl[0], a.Q0h, a.Q0l, (size_t)z * Tt, rr, sel, rsw);
        __syncthreads();
        float* Sb = a.P2 + (size_t)z * Tt * S1c;
        for (int qt = 0; qt < 7; qt++) {
            if (qt < 6)
                fill_tile(Dbh[(qt+1)&1], Dbl[(qt+1)&1], a.Q0h, a.Q0l,
                          (size_t)z * Tt + (qt+1) * 64, rr, sel, rsw);
            qk_tile(Dbh[qt&1], Dbl[qt&1], Sth, Stl, Sb, S1c, qt * 64, 0, warp, lane);
            __syncthreads();
        }
    } else {
        // job3: stationary Qs, stream 7 Kc tiles
        fill_tile(Sth, Stl, a.Qsh, a.Qsl, (size_t)z * S1c, rr, sel, rsw);
        fill_tile(Dbh[0], Dbl[0], a.Kch, a.Kcl, (size_t)z * Tt, rr, sel, rsw);
        __syncthreads();
        float* Sb = a.P3 + (size_t)z * S1c * Tt;
        for (int mt = 0; mt < 7; mt++) {
            if (mt < 6)
                fill_tile(Dbh[(mt+1)&1], Dbl[(mt+1)&1], a.Kch, a.Kcl,
                          (size_t)z * Tt + (mt+1) * 64, rr, sel, rsw);
            qk_tile(Sth, Stl, Dbh[mt&1], Dbl[mt&1], Sb, Tt, 0, mt * 64, warp, lane);
            __syncthreads();
        }
    }
}

// ================= tensor-core fuse MLP + softmax (R14 best) =================
struct FuseW {
    u32 w1h[2][2], w1l[2][2];
    u32 w2h[2], w2l[2];
    float bj0, bj1, bj8, bj9, bh0, bh1;
};

__device__ __forceinline__ void fuse_load_w(
    FuseW& fw, const float* W1, const float* b1,
    const float* W2, const float* b2, int lane)
{
    int t = lane & 3, g = lane >> 2;
#pragma unroll
    for (int hf = 0; hf < 2; hf++) {
        int J = hf * 8 + g;
        split2(W1[(2*t)*16 + J],     W1[(2*t+1)*16 + J], fw.w1h[hf][0], fw.w1l[hf][0]);
        split2(W1[(8+2*t)*16 + J],   W1[(9+2*t)*16 + J], fw.w1h[hf][1], fw.w1l[hf][1]);
    }
    split2(W2[(2*t)*8 + g],   W2[(2*t+1)*8 + g], fw.w2h[0], fw.w2l[0]);
    split2(W2[(8+2*t)*8 + g], W2[(9+2*t)*8 + g], fw.w2h[1], fw.w2l[1]);
    fw.bj0 = b1[2*t]; fw.bj1 = b1[2*t+1];
    fw.bj8 = b1[8+2*t]; fw.bj9 = b1[9+2*t];
    fw.bh0 = b2[2*t]; fw.bh1 = b2[2*t+1];
}

__device__ __forceinline__ void fuse_group(
    const FuseW& fw,
    const float* Sr0, const float* Sr1,
    const float* Ar0, const float* Ar1,
    int m0, int g, float* F)
{
    u32 ah[4], al[4];
    split2(Sr0[m0 + g],     Sr1[m0 + g],     ah[0], al[0]);
    split2(Sr0[m0 + g + 8], Sr1[m0 + g + 8], ah[1], al[1]);
    split2(Ar0[m0 + g],     Ar1[m0 + g],     ah[2], al[2]);
    split2(Ar0[m0 + g + 8], Ar1[m0 + g + 8], ah[3], al[3]);
    float D0[4] = {fw.bj0, fw.bj1, fw.bj0, fw.bj1};
    float D1[4] = {fw.bj8, fw.bj9, fw.bj8, fw.bj9};
    mma_bf16(D0, ah, fw.w1h[0][0], fw.w1h[0][1]);
    mma_bf16(D0, ah, fw.w1l[0][0], fw.w1l[0][1]);
    mma_bf16(D0, al, fw.w1h[0][0], fw.w1h[0][1]);
    mma_bf16(D1, ah, fw.w1h[1][0], fw.w1h[1][1]);
    mma_bf16(D1, ah, fw.w1l[1][0], fw.w1l[1][1]);
    mma_bf16(D1, al, fw.w1h[1][0], fw.w1h[1][1]);
#pragma unroll
    for (int i = 0; i < 4; i++) { D0[i] = fmaxf(D0[i], 0.f); D1[i] = fmaxf(D1[i], 0.f); }
    u32 a2h[4], a2l[4];
    split2(D0[0], D0[1], a2h[0], a2l[0]);
    split2(D0[2], D0[3], a2h[1], a2l[1]);
    split2(D1[0], D1[1], a2h[2], a2l[2]);
    split2(D1[2], D1[3], a2h[3], a2l[3]);
    F[0] = fw.bh0; F[1] = fw.bh1; F[2] = fw.bh0; F[3] = fw.bh1;
    mma_bf16(F, a2h, fw.w2h[0], fw.w2h[1]);
    mma_bf16(F, a2h, fw.w2l[0], fw.w2l[1]);
    mma_bf16(F, a2l, fw.w2h[0], fw.w2h[1]);
}

// jobs 1 & 3: NK=448. 224 threads (7 warps), one (b,n) per block.
__global__ __launch_bounds__(224) void fuse_big(
    const float* __restrict__ P1, const float* __restrict__ P3,
    const float* __restrict__ aux,
    bf16* __restrict__ P1hd, bf16* __restrict__ P1ld,
    bf16* __restrict__ P3hd, bf16* __restrict__ P3ld,
    const float* __restrict__ W1, const float* __restrict__ b1,
    const float* __restrict__ W2, const float* __restrict__ b2)
{
    __shared__ __align__(16) float fs[8][448];
    const int tid = threadIdx.x;
    const int warp = tid >> 5, lane = tid & 31;
    const int t = lane & 3, g = lane >> 2;

    int blk = blockIdx.x;
    const float* S; bf16 *Ph, *Pl;
    int b, n, Nq, qn;
    if (blk < 16 * 448) {
        b = blk / 448; n = blk % 448;
        S = P1; Ph = P1hd; Pl = P1ld; Nq = Tt; qn = S1c;
    } else {
        blk -= 16 * 448;
        b = blk / 64; n = blk % 64;
        S = P3; Ph = P3hd; Pl = P3ld; Nq = S1c; qn = 0;
    }

    FuseW fw;
    fuse_load_w(fw, W1, b1, W2, b2, lane);

    const float* Sr0 = S + ((size_t)((2*t)   * 16 + b) * Nq + n) * 448;
    const float* Sr1 = S + ((size_t)((2*t+1) * 16 + b) * Nq + n) * 448;
    const float* Ar0 = aux + ((size_t)((2*t)   * 16 + b) * 512 + qn + n) * 512 + S1c;
    const float* Ar1 = aux + ((size_t)((2*t+1) * 16 + b) * 512 + qn + n) * 512 + S1c;

#pragma unroll
    for (int gi = 0; gi < 4; gi++) {
        int m0 = (warp + 7 * gi) * 16;
        float F[4];
        fuse_group(fw, Sr0, Sr1, Ar0, Ar1, m0, g, F);
        fs[2*t]   [m0 + g]     = F[0];
        fs[2*t+1] [m0 + g]     = F[1];
        fs[2*t]   [m0 + g + 8] = F[2];
        fs[2*t+1] [m0 + g + 8] = F[3];
    }
    __syncthreads();

    for (int row = warp; row < 8; row += 7) {
        float* frow = fs[row];
        float mx = -3.0e38f;
        for (int m = lane; m < 448; m += 32) mx = fmaxf(mx, frow[m]);
#pragma unroll
        for (int o = 16; o > 0; o >>= 1) mx = fmaxf(mx, __shfl_xor_sync(0xffffffffu, mx, o));
        float sum = 0.f;
        for (int m = lane; m < 448; m += 32) {
            float ev = __expf(frow[m] - mx);
            frow[m] = ev;
            sum += ev;
        }
#pragma unroll
        for (int o = 16; o > 0; o >>= 1) sum += __shfl_xor_sync(0xffffffffu, sum, o);
        float inv = 1.f / sum;
        size_t base = ((size_t)(row * 16 + b) * Nq + n) * 448;
        for (int m = lane; m < 448; m += 32) {
            float p = frow[m] * inv;
            bf16 h = __float2bfloat16(p);
            Ph[base + m] = h;
            Pl[base + m] = __float2bfloat16(p - __bfloat162float(h));
        }
    }
}

// job 2: NK=64. 256 threads (8 warps); warp w owns n-row n0+w.
__global__ __launch_bounds__(256) void fuse_small(
    const float* __restrict__ P2, const float* __restrict__ aux,
    bf16* __restrict__ P2hd, bf16* __restrict__ P2ld,
    const float* __restrict__ W1, const float* __restrict__ b1,
    const float* __restrict__ W2, const float* __restrict__ b2)
{
    __shared__ __align__(16) float fs[8][8][64];
    const int tid = threadIdx.x;
    const int warp = tid >> 5, lane = tid & 31;
    const int t = lane & 3, g = lane >> 2;

    const int b  = blockIdx.x / 56;
    const int n0 = (blockIdx.x % 56) * 8;
    const int n  = n0 + warp;

    FuseW fw;
    fuse_load_w(fw, W1, b1, W2, b2, lane);

    const float* Sr0 = P2 + ((size_t)((2*t)   * 16 + b) * Tt + n) * 64;
    const float* Sr1 = P2 + ((size_t)((2*t+1) * 16 + b) * Tt + n) * 64;
    const float* Ar0 = aux + ((size_t)((2*t)   * 16 + b) * 512 + S1c + n) * 512;
    const float* Ar1 = aux + ((size_t)((2*t+1) * 16 + b) * 512 + S1c + n) * 512;

#pragma unroll
    for (int gi = 0; gi < 4; gi++) {
        int m0 = gi * 16;
        float F[4];
        fuse_group(fw, Sr0, Sr1, Ar0, Ar1, m0, g, F);
        fs[warp][2*t]   [m0 + g]     = F[0];
        fs[warp][2*t+1] [m0 + g]     = F[1];
        fs[warp][2*t]   [m0 + g + 8] = F[2];
        fs[warp][2*t+1] [m0 + g + 8] = F[3];
    }
    __syncwarp();

#pragma unroll
    for (int hr = 0; hr < 8; hr++) {
        float f1 = fs[warp][hr][lane];
        float f2 = fs[warp][hr][lane + 32];
        float mx = fmaxf(f1, f2);
#pragma unroll
        for (int o = 16; o > 0; o >>= 1) mx = fmaxf(mx, __shfl_xor_sync(0xffffffffu, mx, o));
        float e1 = __expf(f1 - mx), e2 = __expf(f2 - mx);
        float sum = e1 + e2;
#pragma unroll
        for (int o = 16; o > 0; o >>= 1) sum += __shfl_xor_sync(0xffffffffu, sum, o);
        float inv = 1.f / sum;
        float p1 = e1 * inv, p2 = e2 * inv;
        size_t base = ((size_t)(hr * 16 + b) * Tt + n) * 64;
        bf16 h1 = __float2bfloat16(p1), h2 = __float2bfloat16(p2);
        P2hd[base + lane]      = h1;
        P2ld[base + lane]      = __float2bfloat16(p1 - __bfloat162float(h1));
        P2hd[base + lane + 32] = h2;
        P2ld[base + lane + 32] = __float2bfloat16(p2 - __bfloat162float(h2));
    }
}

// ================= merged AV HMMA (double-buffered chunks) =================
struct AVArgs {
    const bf16 *P1h, *P1l, *P2h, *P2l, *P3h, *P3l;
    const bf16 *Vch, *Vcl, *Vsh, *Vsl;
    bf16 *Hhi, *Hlo;
};

struct AVSrc {
    const bf16 *Ph, *Pl, *Vh, *Vl;
    size_t prow, vrow;
    int pstride;
};

__device__ __forceinline__ AVSrc av_src(const AVArgs& a, int x, int z, int n0, int c)
{
    AVSrc s;
    if (x < 7) {
        if (c < 14) {
            s.Ph = a.P1h; s.Pl = a.P1l; s.Vh = a.Vch; s.Vl = a.Vcl;
            s.pstride = Tt;  s.prow = ((size_t)z * Tt + n0) * Tt + c * 32;
            s.vrow = (size_t)z * Tt + c * 32;
        } else {
            s.Ph = a.P2h; s.Pl = a.P2l; s.Vh = a.Vsh; s.Vl = a.Vsl;
            s.pstride = S1c; s.prow = ((size_t)z * Tt + n0) * S1c + (c - 14) * 32;
            s.vrow = (size_t)z * S1c + (c - 14) * 32;
        }
    } else {
        s.Ph = a.P3h; s.Pl = a.P3l; s.Vh = a.Vch; s.Vl = a.Vcl;
        s.pstride = Tt;  s.prow = ((size_t)z * S1c) * Tt + c * 32;
        s.vrow = (size_t)z * Tt + c * 32;
    }
    return s;
}

__device__ __forceinline__ void av_fill(
    bf16 (*Pbh)[ASTR], bf16 (*Pbl)[ASTR],
    bf16 (*Vbh)[ASTR], bf16 (*Vbl)[ASTR],
    const AVSrc& s, int tid)
{
    {
        int rr = tid & 63;
        int sel = tid >> 6;
        int rsw = (rr >> 3) & 3;
        const uint4* ps = (const uint4*)((sel ? s.Pl : s.Ph) + s.prow + (size_t)rr * s.pstride);
        bf16 (*Pd)[ASTR] = sel ? Pbl : Pbh;
#pragma unroll
        for (int g = 0; g < 4; g++) {
            int pg = ((g + rsw) & 3) << 3;
            *(uint4*)&Pd[rr][pg] = ps[g];
        }
    }
    if (tid < 64) {
        int rr = tid & 31;
        int sel = tid >> 5;
        int rsw = (rr >> 3) & 3;
        const uint4* vs = (const uint4*)((sel ? s.Vl : s.Vh) + (s.vrow + rr) * 32);
        bf16 (*Vd)[ASTR] = sel ? Vbl : Vbh;
#pragma unroll
        for (int g = 0; g < 4; g++) {
            int pg = ((g + rsw) & 3) << 3;
            *(uint4*)&Vd[rr][pg] = vs[g];
        }
    }
}

__global__ __launch_bounds__(128) void av_hmma(AVArgs a)
{
    __shared__ __align__(16) bf16 Pbh[2][64][ASTR], Pbl[2][64][ASTR];
    __shared__ __align__(16) bf16 Vbh[2][32][ASTR], Vbl[2][32][ASTR];
    const int x = blockIdx.x, z = blockIdx.y;
    const int hh = z >> 4, bb = z & 15;
    const int tid = threadIdx.x;
    const int warp = tid >> 5, lane = tid & 31;

    int n0, qoff, nchunks;
    if (x < 7) { n0 = x * 64; qoff = S1c; nchunks = 16; }
    else       { n0 = 0;      qoff = 0;   nchunks = 14; }

    float acc[4][4];
#pragma unroll
    for (int nf = 0; nf < 4; nf++)
#pragma unroll
        for (int j = 0; j < 4; j++) acc[nf][j] = 0.f;

    av_fill(Pbh[0], Pbl[0], Vbh[0], Vbl[0], av_src(a, x, z, n0, 0), tid);
    __syncthreads();

    for (int c = 0; c < nchunks; c++) {
        if (c + 1 < nchunks)
            av_fill(Pbh[(c+1)&1], Pbl[(c+1)&1], Vbh[(c+1)&1], Vbl[(c+1)&1],
                    av_src(a, x, z, n0, c + 1), tid);
        const int bu = c & 1;
#pragma unroll
        for (int ks = 0; ks < 2; ks++) {
            u32 ah[4], al[4];
            ldA(ah, Pbh[bu], warp * 16, ks, lane);
            ldA(al, Pbl[bu], warp * 16, ks, lane);
#pragma unroll
            for (int np = 0; np < 2; np++) {
                u32 bh[4], bl[4];
                ldBt(bh, Vbh[bu], np, ks, lane);
                ldBt(bl, Vbl[bu], np, ks, lane);
#pragma unroll
                for (int q = 0; q < 2; q++) {
                    int nf = np * 2 + q;
                    mma_bf16(acc[nf], ah, bh[2*q], bh[2*q+1]);
                    mma_bf16(acc[nf], ah, bl[2*q], bl[2*q+1]);
                    mma_bf16(acc[nf], al, bh[2*q], bh[2*q+1]);
                }
            }
        }
        __syncthreads();
    }
#pragma unroll
    for (int nf = 0; nf < 4; nf++) {
        int e = nf * 8 + (lane & 3) * 2;
        int r0 = n0 + warp * 16 + (lane >> 2);
#pragma unroll
        for (int half = 0; half < 2; half++) {
            int rq = r0 + half * 8;
            float2 v = half ? make_float2(acc[nf][2], acc[nf][3])
                            : make_float2(acc[nf][0], acc[nf][1]);
            size_t idx = ((size_t)(bb * Qq + qoff + rq)) * 256 + hh * 32 + e;
            split_st(a.Hhi, a.Hlo, idx, v);
        }
    }
}

// ---------------- launch ----------------
extern "C" void kernel_launch(void* const* d_in, const int* in_sizes, int n_in,
                              void* d_out, int out_size)
{
    const float* h_fea      = (const float*)d_in[0];
    const float* aux        = (const float*)d_in[1];
    const float* Wq_custom  = (const float*)d_in[2];
    const float* Wq_custom1 = (const float*)d_in[3];
    const float* Wk_custom  = (const float*)d_in[4];
    const float* Wv_custom  = (const float*)d_in[5];
    const float* Wq_charge1 = (const float*)d_in[6];
    const float* Wk_charge  = (const float*)d_in[7];
    const float* Wv_charge  = (const float*)d_in[8];
    const float* W1         = (const float*)d_in[9];
    const float* b1         = (const float*)d_in[10];
    const float* W2         = (const float*)d_in[11];
    const float* b2         = (const float*)d_in[12];
    const float* W_out      = (const float*)d_in[13];
    float* out = (float*)d_out;

    float *P1, *P2, *P3;
    bf16 *Xhi, *Xlo, *Hhi, *Hlo, *Wbh, *Wbl;
    bf16 *Q1h, *Q1l, *Q0h, *Q0l, *Kch, *Kcl, *Vch, *Vcl;
    bf16 *Qsh, *Qsl, *Ksh, *Ksl, *Vsh, *Vsl;
    bf16 *P1h, *P1l, *P2h, *P2l, *P3h, *P3l;
    cudaGetSymbolAddress((void**)&P1, g_P1);
    cudaGetSymbolAddress((void**)&P2, g_P2);
    cudaGetSymbolAddress((void**)&P3, g_P3);
    cudaGetSymbolAddress((void**)&Xhi, g_Xhi);
    cudaGetSymbolAddress((void**)&Xlo, g_Xlo);
    cudaGetSymbolAddress((void**)&Hhi, g_Hhi);
    cudaGetSymbolAddress((void**)&Hlo, g_Hlo);
    cudaGetSymbolAddress((void**)&Wbh, g_Wbh);
    cudaGetSymbolAddress((void**)&Wbl, g_Wbl);
    cudaGetSymbolAddress((void**)&Q1h, g_Q1h);  cudaGetSymbolAddress((void**)&Q1l, g_Q1l);
    cudaGetSymbolAddress((void**)&Q0h, g_Q0h);  cudaGetSymbolAddress((void**)&Q0l, g_Q0l);
    cudaGetSymbolAddress((void**)&Kch, g_Kch);  cudaGetSymbolAddress((void**)&Kcl, g_Kcl);
    cudaGetSymbolAddress((void**)&Vch, g_Vch);  cudaGetSymbolAddress((void**)&Vcl, g_Vcl);
    cudaGetSymbolAddress((void**)&Qsh, g_Qsh);  cudaGetSymbolAddress((void**)&Qsl, g_Qsl);
    cudaGetSymbolAddress((void**)&Ksh, g_Ksh);  cudaGetSymbolAddress((void**)&Ksl, g_Ksl);
    cudaGetSymbolAddress((void**)&Vsh, g_Vsh);  cudaGetSymbolAddress((void**)&Vsl, g_Vsl);
    cudaGetSymbolAddress((void**)&P1h, g_P1h);  cudaGetSymbolAddress((void**)&P1l, g_P1l);
    cudaGetSymbolAddress((void**)&P2h, g_P2h);  cudaGetSymbolAddress((void**)&P2l, g_P2l);
    cudaGetSymbolAddress((void**)&P3h, g_P3h);  cudaGetSymbolAddress((void**)&P3l, g_P3l);

    // 1. input/weight splits
    cvt_split_kernel<<<(Bb*Qq*Dd/4 + 255)/256, 256>>>(h_fea, Xhi, Xlo, Bb*Qq*Dd/4);
    WArgs wa;
    wa.W[0] = Wq_custom1; wa.W[1] = Wq_custom; wa.W[2] = Wk_custom; wa.W[3] = Wv_custom;
    wa.W[4] = Wq_charge1; wa.W[5] = Wk_charge; wa.W[6] = Wv_charge; wa.W[7] = W_out;
    cvt_w_kernel<<<8*256*256/256, 256>>>(wa, Wbh, Wbl);

    // 2. merged projections
    HArgs hp;
    hp.Ahi = Xhi; hp.Alo = Xlo; hp.Bh = Wbh; hp.Bl = Wbl;
    hp.Ofp = nullptr; hp.mode = 0;
    hp.Oh[0] = Q1h; hp.Ol[0] = Q1l;
    hp.Oh[1] = Q0h; hp.Ol[1] = Q0l;
    hp.Oh[2] = Kch; hp.Ol[2] = Kcl;
    hp.Oh[3] = Vch; hp.Ol[3] = Vcl;
    hp.Oh[4] = Qsh; hp.Ol[4] = Qsl;
    hp.Oh[5] = Ksh; hp.Ol[5] = Ksl;
    hp.Oh[6] = Vsh; hp.Ol[6] = Vsl;
    hmma_kernel<<<dim3(64, 16), 128>>>(hp);

    // 3. QK^T (double-buffered streams)
    QKArgs qa;
    qa.Q1h = Q1h; qa.Q1l = Q1l; qa.Q0h = Q0h; qa.Q0l = Q0l; qa.Qsh = Qsh; qa.Qsl = Qsl;
    qa.Kch = Kch; qa.Kcl = Kcl; qa.Ksh = Ksh; qa.Ksl = Ksl;
    qa.P1 = P1; qa.P2 = P2; qa.P3 = P3;
    qk_hmma<<<dim3(9, 128), 128>>>(qa);

    // 4. tensor-core fuse MLP + softmax (R14 version)
    fuse_big<<<16*448 + 16*64, 224>>>(P1, P3, aux, P1h, P1l, P3h, P3l, W1, b1, W2, b2);
    fuse_small<<<16*56, 256>>>(P2, aux, P2h, P2l, W1, b1, W2, b2);

    // 5. merged AV (double-buffered chunks) -> head splits directly
    AVArgs aa;
    aa.P1h = P1h; aa.P1l = P1l; aa.P2h = P2h; aa.P2l = P2l; aa.P3h = P3h; aa.P3l = P3l;
    aa.Vch = Vch; aa.Vcl = Vcl; aa.Vsh = Vsh; aa.Vsl = Vsl;
    aa.Hhi = Hhi; aa.Hlo = Hlo;
    av_hmma<<<dim3(8, 128), 128>>>(aa);

    // 6. output GEMM
    HArgs ho;
    ho.Ahi = Hhi; ho.Alo = Hlo; ho.Bh = Wbh; ho.Bl = Wbl;
    ho.Ofp = out; ho.mode = 1;
    for (int i = 0; i < 7; i++) { ho.Oh[i] = nullptr; ho.Ol[i] = nullptr; }
    hmma_kernel<<<dim3(64, 4), 128>>>(ho);
}

// round 17
// speedup vs baseline: 1.0226x; 1.0226x over previous
#include <cuda_runtime.h>
#include <cuda_bf16.h>

#define Hh  8
#define Dd  256
#define HDe 32
#define Bb  16
#define Qq  512
#define S1c 64
#define Tt  448

typedef unsigned long long u64;
typedef unsigned int u32;
typedef __nv_bfloat16  bf16;
typedef __nv_bfloat162 bf162;

// ---------------- static scratch ----------------
__device__ float g_P1[128*Tt*Tt];
__device__ float g_P2[128*Tt*S1c];
__device__ float g_P3[128*S1c*Tt];

__device__ bf16 g_Xhi[Bb*Qq*Dd], g_Xlo[Bb*Qq*Dd];
__device__ bf16 g_Hhi[Bb*Qq*Dd], g_Hlo[Bb*Qq*Dd];
__device__ bf16 g_Wbh[8*256*256], g_Wbl[8*256*256];

__device__ bf16 g_Q1h[128*Tt*32],  g_Q1l[128*Tt*32];
__device__ bf16 g_Q0h[128*Tt*32],  g_Q0l[128*Tt*32];
__device__ bf16 g_Kch[128*Tt*32],  g_Kcl[128*Tt*32];
__device__ bf16 g_Vch[128*Tt*32],  g_Vcl[128*Tt*32];
__device__ bf16 g_Qsh[128*S1c*32], g_Qsl[128*S1c*32];
__device__ bf16 g_Ksh[128*S1c*32], g_Ksl[128*S1c*32];
__device__ bf16 g_Vsh[128*S1c*32], g_Vsl[128*S1c*32];

__device__ bf16 g_P1h[128*Tt*Tt],  g_P1l[128*Tt*Tt];
__device__ bf16 g_P2h[128*Tt*S1c], g_P2l[128*Tt*S1c];
__device__ bf16 g_P3h[128*S1c*Tt], g_P3l[128*S1c*Tt];

// ================= conversion kernels =================
__global__ __launch_bounds__(256) void cvt_split_kernel(
    const float* __restrict__ src, bf16* __restrict__ hi,
    bf16* __restrict__ lo, int n4)
{
    int i = blockIdx.x * 256 + threadIdx.x;
    if (i >= n4) return;
    float4 v = ((const float4*)src)[i];
    bf16 h0 = __float2bfloat16(v.x), h1 = __float2bfloat16(v.y);
    bf16 h2 = __float2bfloat16(v.z), h3 = __float2bfloat16(v.w);
    ((bf162*)hi)[i*2]   = bf162(h0, h1);
    ((bf162*)hi)[i*2+1] = bf162(h2, h3);
    ((bf162*)lo)[i*2]   = bf162(__float2bfloat16(v.x - __bfloat162float(h0)),
                                __float2bfloat16(v.y - __bfloat162float(h1)));
    ((bf162*)lo)[i*2+1] = bf162(__float2bfloat16(v.z - __bfloat162float(h2)),
                                __float2bfloat16(v.w - __bfloat162float(h3)));
}

struct WArgs { const float* W[8]; };

__global__ __launch_bounds__(256) void cvt_w_kernel(
    WArgs wa, bf16* __restrict__ bh, bf16* __restrict__ bl)
{
    int i = blockIdx.x * 256 + threadIdx.x;
    int s = i >> 16;
    int r = i & 65535;
    int c = r >> 8, k = r & 255;
    const float* W = wa.W[s];
    float x = (s < 7) ? W[(c >> 5) * 8192 + k * 32 + (c & 31)] : W[k * 256 + c];
    bf16 h = __float2bfloat16(x);
    bh[i] = h;
    bl[i] = __float2bfloat16(x - __bfloat162float(h));
}

// ================= shared HMMA machinery =================
#define ASTR 40

__device__ __forceinline__ u32 smaddr(const void* p) {
    return (u32)__cvta_generic_to_shared(p);
}
__device__ __forceinline__ void ldsm4(u32& r0, u32& r1, u32& r2, u32& r3, u32 a) {
    asm volatile("ldmatrix.sync.aligned.m8n8.x4.shared.b16 {%0,%1,%2,%3},[%4];"
        : "=r"(r0), "=r"(r1), "=r"(r2), "=r"(r3) : "r"(a));
}
__device__ __forceinline__ void ldsm4t(u32& r0, u32& r1, u32& r2, u32& r3, u32 a) {
    asm volatile("ldmatrix.sync.aligned.m8n8.x4.trans.shared.b16 {%0,%1,%2,%3},[%4];"
        : "=r"(r0), "=r"(r1), "=r"(r2), "=r"(r3) : "r"(a));
}

__device__ __forceinline__ void ldA(u32* a, const bf16 (*M)[ASTR], int R0, int ks, int lane) {
    int row = R0 + ((lane >> 3) & 1) * 8 + (lane & 7);
    int kg  = 2 * ks + (lane >> 4);
    ldsm4(a[0], a[1], a[2], a[3], smaddr(&M[row][((kg + (row >> 3)) & 3) << 3]));
}
__device__ __forceinline__ void ldB(u32* b, const bf16 (*M)[ASTR], int N0, int ks, int lane) {
    int row = N0 + (lane >> 4) * 8 + (lane & 7);
    int kg  = 2 * ks + ((lane >> 3) & 1);
    ldsm4(b[0], b[1], b[2], b[3], smaddr(&M[row][((kg + (row >> 3)) & 3) << 3]));
}
__device__ __forceinline__ void ldBt(u32* b, const bf16 (*M)[ASTR], int nfp, int ks, int lane) {
    int row = ks * 16 + ((lane >> 3) & 1) * 8 + (lane & 7);
    int eg  = nfp * 2 + (lane >> 4);
    ldsm4t(b[0], b[1], b[2], b[3], smaddr(&M[row][((eg + (row >> 3)) & 3) << 3]));
}

__device__ __forceinline__ void mma_bf16(float* d, const u32* a, u32 b0, u32 b1) {
    asm volatile(
        "mma.sync.aligned.m16n8k16.row.col.f32.bf16.bf16.f32 "
        "{%0,%1,%2,%3}, {%4,%5,%6,%7}, {%8,%9}, {%0,%1,%2,%3};"
        : "+f"(d[0]), "+f"(d[1]), "+f"(d[2]), "+f"(d[3])
        : "r"(a[0]), "r"(a[1]), "r"(a[2]), "r"(a[3]), "r"(b0), "r"(b1));
}

__device__ __forceinline__ void split_st(bf16* hp, bf16* lp, size_t idx, float2 v) {
    bf16 h0 = __float2bfloat16(v.x), h1 = __float2bfloat16(v.y);
    *(bf162*)(hp + idx) = bf162(h0, h1);
    *(bf162*)(lp + idx) = bf162(__float2bfloat16(v.x - __bfloat162float(h0)),
                                __float2bfloat16(v.y - __bfloat162float(h1)));
}

// pack two fp32 into bf16x2 {lo=x, hi=y} plus residual pair
__device__ __forceinline__ void split2(float x, float y, u32& hi, u32& lo) {
    float xh = __bfloat162float(__float2bfloat16(x));
    float yh = __bfloat162float(__float2bfloat16(y));
    asm("cvt.rn.bf16x2.f32 %0, %1, %2;" : "=r"(hi) : "f"(yh), "f"(xh));
    asm("cvt.rn.bf16x2.f32 %0, %1, %2;" : "=r"(lo) : "f"(y - yh), "f"(x - xh));
}

// fill one 64-row tile (hi or lo selected by sel) from [(rowbase+rr)*32] source
__device__ __forceinline__ void fill_tile(
    bf16 (*Dh)[ASTR], bf16 (*Dl)[ASTR],
    const bf16* __restrict__ srcH, const bf16* __restrict__ srcL,
    size_t rowbase, int rr, int sel, int rsw)
{
    const uint4* s = (const uint4*)((sel ? srcL : srcH) + (rowbase + rr) * 32);
    bf16 (*D)[ASTR] = sel ? Dl : Dh;
#pragma unroll
    for (int g = 0; g < 4; g++) {
        int pg = ((g + rsw) & 3) << 3;
        *(uint4*)&D[rr][pg] = s[g];
    }
}

// ================= proj/out HMMA kernel =================
struct HArgs {
    const bf16 *Ahi, *Alo;
    const bf16 *Bh, *Bl;
    float* Ofp;
    bf16 *Oh[7], *Ol[7];
    int mode;
};

__global__ __launch_bounds__(128) void hmma_kernel(HArgs args)
{
    __shared__ __align__(16) bf16 Ah[128][ASTR], Al[128][ASTR];
    __shared__ __align__(16) bf16 Bhs[64][ASTR], Bls[64][ASTR];
    const int x = blockIdx.x, y = blockIdx.y;
    int set, col0, TL, qoff, m0;
    if (args.mode == 0) {
        if (x < 56) { set = y >> 2; col0 = (y & 3) * 64; TL = Tt; qoff = S1c; m0 = x * 128; }
        else {
            if (y >= 12) return;
            set = 4 + (y >> 2); col0 = (y & 3) * 64; TL = S1c; qoff = 0; m0 = (x - 56) * 128;
        }
    } else { set = 7; col0 = y * 64; TL = Qq; qoff = 0; m0 = x * 128; }

    const int tid = threadIdx.x;
    const int warp = tid >> 5, lane = tid & 31;

    float acc[2][8][4];
#pragma unroll
    for (int mf = 0; mf < 2; mf++)
#pragma unroll
        for (int nf = 0; nf < 8; nf++)
#pragma unroll
            for (int j = 0; j < 4; j++) acc[mf][nf][j] = 0.f;

    int t = m0 + tid;
    int ab = t / TL;
    size_t arow = ((size_t)ab * Qq + qoff + (t - ab * TL)) * 256;
    const int br = tid & 63;
    const bf16* Bsrc = ((tid < 64) ? args.Bh : args.Bl) + (size_t)set * 65536 + (size_t)(col0 + br) * 256;
    const int rswA = (tid >> 3) & 3;
    const int rswB = (br >> 3) & 3;

    for (int k0 = 0; k0 < 256; k0 += 32) {
        if (k0) __syncthreads();
        const uint4* sAh = (const uint4*)(args.Ahi + arow + k0);
        const uint4* sAl = (const uint4*)(args.Alo + arow + k0);
#pragma unroll
        for (int g = 0; g < 4; g++) {
            int pg = ((g + rswA) & 3) << 3;
            *(uint4*)&Ah[tid][pg] = sAh[g];
            *(uint4*)&Al[tid][pg] = sAl[g];
        }
        {
            const uint4* sB = (const uint4*)(Bsrc + k0);
            bf16 (*Bd)[ASTR] = (tid < 64) ? Bhs : Bls;
#pragma unroll
            for (int g = 0; g < 4; g++) {
                int pg = ((g + rswB) & 3) << 3;
                *(uint4*)&Bd[br][pg] = sB[g];
            }
        }
        __syncthreads();
#pragma unroll
        for (int ks = 0; ks < 2; ks++) {
            u32 ah[2][4], al[2][4];
            ldA(ah[0], Ah, warp * 32,      ks, lane);
            ldA(ah[1], Ah, warp * 32 + 16, ks, lane);
            ldA(al[0], Al, warp * 32,      ks, lane);
            ldA(al[1], Al, warp * 32 + 16, ks, lane);
#pragma unroll
            for (int np = 0; np < 4; np++) {
                u32 bh[4], bl[4];
                ldB(bh, Bhs, np * 16, ks, lane);
                ldB(bl, Bls, np * 16, ks, lane);
#pragma unroll
                for (int q = 0; q < 2; q++) {
                    int nf = np * 2 + q;
#pragma unroll
                    for (int mf = 0; mf < 2; mf++) {
                        mma_bf16(acc[mf][nf], ah[mf], bh[2*q], bh[2*q+1]);
                        mma_bf16(acc[mf][nf], ah[mf], bl[2*q], bl[2*q+1]);
                        mma_bf16(acc[mf][nf], al[mf], bh[2*q], bh[2*q+1]);
                    }
                }
            }
        }
    }

#pragma unroll
    for (int mf = 0; mf < 2; mf++) {
#pragma unroll
        for (int nf = 0; nf < 8; nf++) {
            int lc = nf * 8 + (lane & 3) * 2;
            int t0 = m0 + warp * 32 + mf * 16 + (lane >> 2);
            int t1 = t0 + 8;
            float2 v0 = make_float2(acc[mf][nf][0], acc[mf][nf][1]);
            float2 v1 = make_float2(acc[mf][nf][2], acc[mf][nf][3]);
            if (args.mode == 0) {
                int c = col0 + lc;
                int h = c >> 5, e = c & 31;
                int b0i = t0 / TL, n0i = t0 - b0i * TL;
                int b1i = t1 / TL, n1i = t1 - b1i * TL;
                size_t i0 = (((size_t)h * Bb + b0i) * TL + n0i) * 32 + e;
                size_t i1 = (((size_t)h * Bb + b1i) * TL + n1i) * 32 + e;
                split_st(args.Oh[set], args.Ol[set], i0, v0);
                split_st(args.Oh[set], args.Ol[set], i1, v1);
            } else {
                int d = col0 + lc;
                *(float2*)(args.Ofp + (size_t)t0 * 256 + d) = v0;
                *(float2*)(args.Ofp + (size_t)t1 * 256 + d) = v1;
            }
        }
    }
}

// ================= QK^T HMMA (stationary-tile loop, R14) =================
struct QKArgs {
    const bf16 *Q1h, *Q1l, *Q0h, *Q0l, *Qsh, *Qsl;
    const bf16 *Kch, *Kcl, *Ksh, *Ksl;
    float *P1, *P2, *P3;
};

__device__ __forceinline__ void qk_tile(
    const bf16 (*Qhs)[ASTR], const bf16 (*Qls)[ASTR],
    const bf16 (*Khs)[ASTR], const bf16 (*Kls)[ASTR],
    float* Sb, int Nk, int row0, int col0, int warp, int lane)
{
    float acc[8][4];
#pragma unroll
    for (int nf = 0; nf < 8; nf++)
#pragma unroll
        for (int j = 0; j < 4; j++) acc[nf][j] = 0.f;
#pragma unroll
    for (int ks = 0; ks < 2; ks++) {
        u32 ah[4], al[4];
        ldA(ah, Qhs, warp * 16, ks, lane);
        ldA(al, Qls, warp * 16, ks, lane);
#pragma unroll
        for (int np = 0; np < 4; np++) {
            u32 bh[4], bl[4];
            ldB(bh, Khs, np * 16, ks, lane);
            ldB(bl, Kls, np * 16, ks, lane);
#pragma unroll
            for (int q = 0; q < 2; q++) {
                int nf = np * 2 + q;
                mma_bf16(acc[nf], ah, bh[2*q], bh[2*q+1]);
                mma_bf16(acc[nf], ah, bl[2*q], bl[2*q+1]);
                mma_bf16(acc[nf], al, bh[2*q], bh[2*q+1]);
            }
        }
    }
#pragma unroll
    for (int nf = 0; nf < 8; nf++) {
        int col = col0 + nf * 8 + (lane & 3) * 2;
        int r0 = row0 + warp * 16 + (lane >> 2);
        *(float2*)(Sb + (size_t)r0 * Nk + col)       = make_float2(acc[nf][0], acc[nf][1]);
        *(float2*)(Sb + (size_t)(r0 + 8) * Nk + col) = make_float2(acc[nf][2], acc[nf][3]);
    }
}

__global__ __launch_bounds__(128) void qk_hmma(QKArgs a)
{
    __shared__ __align__(16) bf16 Qhs[64][ASTR], Qls[64][ASTR];
    __shared__ __align__(16) bf16 Khs[64][ASTR], Kls[64][ASTR];
    const int x = blockIdx.x, z = blockIdx.y;
    const int tid = threadIdx.x;
    const int warp = tid >> 5, lane = tid & 31;
    const int rr = tid & 63;
    const int sel = tid >> 6;
    const int rsw = (rr >> 3) & 3;

    if (x < 7) {
        fill_tile(Qhs, Qls, a.Q1h, a.Q1l, (size_t)z * Tt + x * 64, rr, sel, rsw);
        float* Sb = a.P1 + (size_t)z * Tt * Tt;
        for (int mt = 0; mt < 7; mt++) {
            if (mt) __syncthreads();
            fill_tile(Khs, Kls, a.Kch, a.Kcl, (size_t)z * Tt + mt * 64, rr, sel, rsw);
            __syncthreads();
            qk_tile(Qhs, Qls, Khs, Kls, Sb, Tt, x * 64, mt * 64, warp, lane);
        }
    } else if (x == 7) {
        fill_tile(Khs, Kls, a.Ksh, a.Ksl, (size_t)z * S1c, rr, sel, rsw);
        float* Sb = a.P2 + (size_t)z * Tt * S1c;
        for (int qt = 0; qt < 7; qt++) {
            if (qt) __syncthreads();
            fill_tile(Qhs, Qls, a.Q0h, a.Q0l, (size_t)z * Tt + qt * 64, rr, sel, rsw);
            __syncthreads();
            qk_tile(Qhs, Qls, Khs, Kls, Sb, S1c, qt * 64, 0, warp, lane);
        }
    } else {
        fill_tile(Qhs, Qls, a.Qsh, a.Qsl, (size_t)z * S1c, rr, sel, rsw);
        float* Sb = a.P3 + (size_t)z * S1c * Tt;
        for (int mt = 0; mt < 7; mt++) {
            if (mt) __syncthreads();
            fill_tile(Khs, Kls, a.Kch, a.Kcl, (size_t)z * Tt + mt * 64, rr, sel, rsw);
            __syncthreads();
            qk_tile(Qhs, Qls, Khs, Kls, Sb, Tt, 0, mt * 64, warp, lane);
        }
    }
}

// ================= tensor-core fuse MLP + softmax (prefetched inputs) ==========
struct FuseW {
    u32 w1h[2][2], w1l[2][2];
    u32 w2h[2], w2l[2];
    float bj0, bj1, bj8, bj9, bh0, bh1;
};

__device__ __forceinline__ void fuse_load_w(
    FuseW& fw, const float* W1, const float* b1,
    const float* W2, const float* b2, int lane)
{
    int t = lane & 3, g = lane >> 2;
#pragma unroll
    for (int hf = 0; hf < 2; hf++) {
        int J = hf * 8 + g;
        split2(W1[(2*t)*16 + J],     W1[(2*t+1)*16 + J], fw.w1h[hf][0], fw.w1l[hf][0]);
        split2(W1[(8+2*t)*16 + J],   W1[(9+2*t)*16 + J], fw.w1h[hf][1], fw.w1l[hf][1]);
    }
    split2(W2[(2*t)*8 + g],   W2[(2*t+1)*8 + g], fw.w2h[0], fw.w2l[0]);
    split2(W2[(8+2*t)*8 + g], W2[(9+2*t)*8 + g], fw.w2h[1], fw.w2l[1]);
    fw.bj0 = b1[2*t]; fw.bj1 = b1[2*t+1];
    fw.bj8 = b1[8+2*t]; fw.bj9 = b1[9+2*t];
    fw.bh0 = b2[2*t]; fw.bh1 = b2[2*t+1];
}

// compute one group from 8 prefetched values:
// x[0]=S0[m+g] x[1]=S0[m+g+8] x[2]=S1[m+g] x[3]=S1[m+g+8]
// x[4]=A0[m+g] x[5]=A0[m+g+8] x[6]=A1[m+g] x[7]=A1[m+g+8]
__device__ __forceinline__ void fuse_group(
    const FuseW& fw, const float* x, float* F)
{
    u32 ah[4], al[4];
    split2(x[0], x[2], ah[0], al[0]);
    split2(x[1], x[3], ah[1], al[1]);
    split2(x[4], x[6], ah[2], al[2]);
    split2(x[5], x[7], ah[3], al[3]);
    float D0[4] = {fw.bj0, fw.bj1, fw.bj0, fw.bj1};
    float D1[4] = {fw.bj8, fw.bj9, fw.bj8, fw.bj9};
    mma_bf16(D0, ah, fw.w1h[0][0], fw.w1h[0][1]);
    mma_bf16(D0, ah, fw.w1l[0][0], fw.w1l[0][1]);
    mma_bf16(D0, al, fw.w1h[0][0], fw.w1h[0][1]);
    mma_bf16(D1, ah, fw.w1h[1][0], fw.w1h[1][1]);
    mma_bf16(D1, ah, fw.w1l[1][0], fw.w1l[1][1]);
    mma_bf16(D1, al, fw.w1h[1][0], fw.w1h[1][1]);
#pragma unroll
    for (int i = 0; i < 4; i++) { D0[i] = fmaxf(D0[i], 0.f); D1[i] = fmaxf(D1[i], 0.f); }
    u32 a2h[4], a2l[4];
    split2(D0[0], D0[1], a2h[0], a2l[0]);
    split2(D0[2], D0[3], a2h[1], a2l[1]);
    split2(D1[0], D1[1], a2h[2], a2l[2]);
    split2(D1[2], D1[3], a2h[3], a2l[3]);
    F[0] = fw.bh0; F[1] = fw.bh1; F[2] = fw.bh0; F[3] = fw.bh1;
    mma_bf16(F, a2h, fw.w2h[0], fw.w2h[1]);
    mma_bf16(F, a2h, fw.w2l[0], fw.w2l[1]);
    mma_bf16(F, a2l, fw.w2h[0], fw.w2h[1]);
}

// jobs 1 & 3: NK=448. 224 threads (7 warps), one (b,n) per block.
// All 32 per-thread gmem loads batched up front (4x memory-level parallelism).
__global__ __launch_bounds__(224) void fuse_big(
    const float* __restrict__ P1, const float* __restrict__ P3,
    const float* __restrict__ aux,
    bf16* __restrict__ P1hd, bf16* __restrict__ P1ld,
    bf16* __restrict__ P3hd, bf16* __restrict__ P3ld,
    const float* __restrict__ W1, const float* __restrict__ b1,
    const float* __restrict__ W2, const float* __restrict__ b2)
{
    __shared__ __align__(16) float fs[8][448];
    const int tid = threadIdx.x;
    const int warp = tid >> 5, lane = tid & 31;
    const int t = lane & 3, g = lane >> 2;

    int blk = blockIdx.x;
    const float* S; bf16 *Ph, *Pl;
    int b, n, Nq, qn;
    if (blk < 16 * 448) {
        b = blk / 448; n = blk % 448;
        S = P1; Ph = P1hd; Pl = P1ld; Nq = Tt; qn = S1c;
    } else {
        blk -= 16 * 448;
        b = blk / 64; n = blk % 64;
        S = P3; Ph = P3hd; Pl = P3ld; Nq = S1c; qn = 0;
    }

    const float* Sr0 = S + ((size_t)((2*t)   * 16 + b) * Nq + n) * 448;
    const float* Sr1 = S + ((size_t)((2*t+1) * 16 + b) * Nq + n) * 448;
    const float* Ar0 = aux + ((size_t)((2*t)   * 16 + b) * 512 + qn + n) * 512 + S1c;
    const float* Ar1 = aux + ((size_t)((2*t+1) * 16 + b) * 512 + qn + n) * 512 + S1c;

    // batched prefetch: 32 independent loads in flight
    float pv[4][8];
#pragma unroll
    for (int gi = 0; gi < 4; gi++) {
        int m0 = (warp + 7 * gi) * 16;
        pv[gi][0] = Sr0[m0 + g];  pv[gi][1] = Sr0[m0 + g + 8];
        pv[gi][2] = Sr1[m0 + g];  pv[gi][3] = Sr1[m0 + g + 8];
        pv[gi][4] = Ar0[m0 + g];  pv[gi][5] = Ar0[m0 + g + 8];
        pv[gi][6] = Ar1[m0 + g];  pv[gi][7] = Ar1[m0 + g + 8];
    }

    FuseW fw;
    fuse_load_w(fw, W1, b1, W2, b2, lane);

#pragma unroll
    for (int gi = 0; gi < 4; gi++) {
        int m0 = (warp + 7 * gi) * 16;
        float F[4];
        fuse_group(fw, pv[gi], F);
        fs[2*t]   [m0 + g]     = F[0];
        fs[2*t+1] [m0 + g]     = F[1];
        fs[2*t]   [m0 + g + 8] = F[2];
        fs[2*t+1] [m0 + g + 8] = F[3];
    }
    __syncthreads();

    for (int row = warp; row < 8; row += 7) {
        float* frow = fs[row];
        float mx = -3.0e38f;
        for (int m = lane; m < 448; m += 32) mx = fmaxf(mx, frow[m]);
#pragma unroll
        for (int o = 16; o > 0; o >>= 1) mx = fmaxf(mx, __shfl_xor_sync(0xffffffffu, mx, o));
        float sum = 0.f;
        for (int m = lane; m < 448; m += 32) {
            float ev = __expf(frow[m] - mx);
            frow[m] = ev;
            sum += ev;
        }
#pragma unroll
        for (int o = 16; o > 0; o >>= 1) sum += __shfl_xor_sync(0xffffffffu, sum, o);
        float inv = 1.f / sum;
        size_t base = ((size_t)(row * 16 + b) * Nq + n) * 448;
        for (int m = lane; m < 448; m += 32) {
            float p = frow[m] * inv;
            bf16 h = __float2bfloat16(p);
            Ph[base + m] = h;
            Pl[base + m] = __float2bfloat16(p - __bfloat162float(h));
        }
    }
}

// job 2: NK=64. 256 threads (8 warps); warp w owns n-row n0+w. Prefetched loads.
__global__ __launch_bounds__(256) void fuse_small(
    const float* __restrict__ P2, const float* __restrict__ aux,
    bf16* __restrict__ P2hd, bf16* __restrict__ P2ld,
    const float* __restrict__ W1, const float* __restrict__ b1,
    const float* __restrict__ W2, const float* __restrict__ b2)
{
    __shared__ __align__(16) float fs[8][8][64];
    const int tid = threadIdx.x;
    const int warp = tid >> 5, lane = tid & 31;
    const int t = lane & 3, g = lane >> 2;

    const int b  = blockIdx.x / 56;
    const int n0 = (blockIdx.x % 56) * 8;
    const int n  = n0 + warp;

    const float* Sr0 = P2 + ((size_t)((2*t)   * 16 + b) * Tt + n) * 64;
    const float* Sr1 = P2 + ((size_t)((2*t+1) * 16 + b) * Tt + n) * 64;
    const float* Ar0 = aux + ((size_t)((2*t)   * 16 + b) * 512 + S1c + n) * 512;
    const float* Ar1 = aux + ((size_t)((2*t+1) * 16 + b) * 512 + S1c + n) * 512;

    float pv[4][8];
#pragma unroll
    for (int gi = 0; gi < 4; gi++) {
        int m0 = gi * 16;
        pv[gi][0] = Sr0[m0 + g];  pv[gi][1] = Sr0[m0 + g + 8];
        pv[gi][2] = Sr1[m0 + g];  pv[gi][3] = Sr1[m0 + g + 8];
        pv[gi][4] = Ar0[m0 + g];  pv[gi][5] = Ar0[m0 + g + 8];
        pv[gi][6] = Ar1[m0 + g];  pv[gi][7] = Ar1[m0 + g + 8];
    }

    FuseW fw;
    fuse_load_w(fw, W1, b1, W2, b2, lane);

#pragma unroll
    for (int gi = 0; gi < 4; gi++) {
        int m0 = gi * 16;
        float F[4];
        fuse_group(fw, pv[gi], F);
        fs[warp][2*t]   [m0 + g]     = F[0];
        fs[warp][2*t+1] [m0 + g]     = F[1];
        fs[warp][2*t]   [m0 + g + 8] = F[2];
        fs[warp][2*t+1] [m0 + g + 8] = F[3];
    }
    __syncwarp();

#pragma unroll
    for (int hr = 0; hr < 8; hr++) {
        float f1 = fs[warp][hr][lane];
        float f2 = fs[warp][hr][lane + 32];
        float mx = fmaxf(f1, f2);
#pragma unroll
        for (int o = 16; o > 0; o >>= 1) mx = fmaxf(mx, __shfl_xor_sync(0xffffffffu, mx, o));
        float e1 = __expf(f1 - mx), e2 = __expf(f2 - mx);
        float sum = e1 + e2;
#pragma unroll
        for (int o = 16; o > 0; o >>= 1) sum += __shfl_xor_sync(0xffffffffu, sum, o);
        float inv = 1.f / sum;
        float p1 = e1 * inv, p2 = e2 * inv;
        size_t base = ((size_t)(hr * 16 + b) * Tt + n) * 64;
        bf16 h1 = __float2bfloat16(p1), h2 = __float2bfloat16(p2);
        P2hd[base + lane]      = h1;
        P2ld[base + lane]      = __float2bfloat16(p1 - __bfloat162float(h1));
        P2hd[base + lane + 32] = h2;
        P2ld[base + lane + 32] = __float2bfloat16(p2 - __bfloat162float(h2));
    }
}

// ================= merged AV HMMA (R14 serial-fill version) =================
struct AVArgs {
    const bf16 *P1h, *P1l, *P2h, *P2l, *P3h, *P3l;
    const bf16 *Vch, *Vcl, *Vsh, *Vsl;
    bf16 *Hhi, *Hlo;
};
__global__ __launch_bounds__(128) void av_hmma(AVArgs a)
{
    __shared__ __align__(16) bf16 Phs[64][ASTR], Pls[64][ASTR];
    __shared__ __align__(16) bf16 Vhs[32][ASTR], Vls[32][ASTR];
    const int x = blockIdx.x, z = blockIdx.y;
    const int hh = z >> 4, bb = z & 15;
    const int tid = threadIdx.x;
    const int warp = tid >> 5, lane = tid & 31;

    int n0, qoff, nchunks;
    if (x < 7) { n0 = x * 64; qoff = S1c; nchunks = 16; }
    else       { n0 = 0;      qoff = 0;   nchunks = 14; }

    float acc[4][4];
#pragma unroll
    for (int nf = 0; nf < 4; nf++)
#pragma unroll
        for (int j = 0; j < 4; j++) acc[nf][j] = 0.f;

    for (int c = 0; c < nchunks; c++) {
        if (c) __syncthreads();
        const bf16 *Ph, *Pl, *Vh, *Vl;
        size_t prow; int pstride; size_t vrow;
        if (x < 7) {
            if (c < 14) {
                Ph = a.P1h; Pl = a.P1l; Vh = a.Vch; Vl = a.Vcl;
                pstride = Tt;  prow = ((size_t)z * Tt + n0) * Tt + c * 32;
                vrow = (size_t)z * Tt + c * 32;
            } else {
                Ph = a.P2h; Pl = a.P2l; Vh = a.Vsh; Vl = a.Vsl;
                pstride = S1c; prow = ((size_t)z * Tt + n0) * S1c + (c - 14) * 32;
                vrow = (size_t)z * S1c + (c - 14) * 32;
            }
        } else {
            Ph = a.P3h; Pl = a.P3l; Vh = a.Vch; Vl = a.Vcl;
            pstride = Tt;  prow = ((size_t)z * S1c) * Tt + c * 32;
            vrow = (size_t)z * Tt + c * 32;
        }
        {
            int rr = tid & 63;
            int sel = tid >> 6;
            int rsw = (rr >> 3) & 3;
            const uint4* ps = (const uint4*)((sel ? Pl : Ph) + prow + (size_t)rr * pstride);
            bf16 (*Pd)[ASTR] = sel ? Pls : Phs;
#pragma unroll
            for (int g = 0; g < 4; g++) {
                int pg = ((g + rsw) & 3) << 3;
                *(uint4*)&Pd[rr][pg] = ps[g];
            }
        }
        if (tid < 64) {
            int rr = tid & 31;
            int sel = tid >> 5;
            int rsw = (rr >> 3) & 3;
            const uint4* vs = (const uint4*)((sel ? Vl : Vh) + (vrow + rr) * 32);
            bf16 (*Vd)[ASTR] = sel ? Vls : Vhs;
#pragma unroll
            for (int g = 0; g < 4; g++) {
                int pg = ((g + rsw) & 3) << 3;
                *(uint4*)&Vd[rr][pg] = vs[g];
            }
        }
        __syncthreads();
#pragma unroll
        for (int ks = 0; ks < 2; ks++) {
            u32 ah[4], al[4];
            ldA(ah, Phs, warp * 16, ks, lane);
            ldA(al, Pls, warp * 16, ks, lane);
#pragma unroll
            for (int np = 0; np < 2; np++) {
                u32 bh[4], bl[4];
                ldBt(bh, Vhs, np, ks, lane);
                ldBt(bl, Vls, np, ks, lane);
#pragma unroll
                for (int q = 0; q < 2; q++) {
                    int nf = np * 2 + q;
                    mma_bf16(acc[nf], ah, bh[2*q], bh[2*q+1]);
                    mma_bf16(acc[nf], ah, bl[2*q], bl[2*q+1]);
                    mma_bf16(acc[nf], al, bh[2*q], bh[2*q+1]);
                }
            }
        }
    }
#pragma unroll
    for (int nf = 0; nf < 4; nf++) {
        int e = nf * 8 + (lane & 3) * 2;
        int r0 = n0 + warp * 16 + (lane >> 2);
#pragma unroll
        for (int half = 0; half < 2; half++) {
            int rq = r0 + half * 8;
            float2 v = half ? make_float2(acc[nf][2], acc[nf][3])
                            : make_float2(acc[nf][0], acc[nf][1]);
            size_t idx = ((size_t)(bb * Qq + qoff + rq)) * 256 + hh * 32 + e;
            split_st(a.Hhi, a.Hlo, idx, v);
        }
    }
}

// ---------------- launch ----------------
extern "C" void kernel_launch(void* const* d_in, const int* in_sizes, int n_in,
                              void* d_out, int out_size)
{
    const float* h_fea      = (const float*)d_in[0];
    const float* aux        = (const float*)d_in[1];
    const float* Wq_custom  = (const float*)d_in[2];
    const float* Wq_custom1 = (const float*)d_in[3];
    const float* Wk_custom  = (const float*)d_in[4];
    const float* Wv_custom  = (const float*)d_in[5];
    const float* Wq_charge1 = (const float*)d_in[6];
    const float* Wk_charge  = (const float*)d_in[7];
    const float* Wv_charge  = (const float*)d_in[8];
    const float* W1         = (const float*)d_in[9];
    const float* b1         = (const float*)d_in[10];
    const float* W2         = (const float*)d_in[11];
    const float* b2         = (const float*)d_in[12];
    const float* W_out      = (const float*)d_in[13];
    float* out = (float*)d_out;

    float *P1, *P2, *P3;
    bf16 *Xhi, *Xlo, *Hhi, *Hlo, *Wbh, *Wbl;
    bf16 *Q1h, *Q1l, *Q0h, *Q0l, *Kch, *Kcl, *Vch, *Vcl;
    bf16 *Qsh, *Qsl, *Ksh, *Ksl, *Vsh, *Vsl;
    bf16 *P1h, *P1l, *P2h, *P2l, *P3h, *P3l;
    cudaGetSymbolAddress((void**)&P1, g_P1);
    cudaGetSymbolAddress((void**)&P2, g_P2);
    cudaGetSymbolAddress((void**)&P3, g_P3);
    cudaGetSymbolAddress((void**)&Xhi, g_Xhi);
    cudaGetSymbolAddress((void**)&Xlo, g_Xlo);
    cudaGetSymbolAddress((void**)&Hhi, g_Hhi);
    cudaGetSymbolAddress((void**)&Hlo, g_Hlo);
    cudaGetSymbolAddress((void**)&Wbh, g_Wbh);
    cudaGetSymbolAddress((void**)&Wbl, g_Wbl);
    cudaGetSymbolAddress((void**)&Q1h, g_Q1h);  cudaGetSymbolAddress((void**)&Q1l, g_Q1l);
    cudaGetSymbolAddress((void**)&Q0h, g_Q0h);  cudaGetSymbolAddress((void**)&Q0l, g_Q0l);
    cudaGetSymbolAddress((void**)&Kch, g_Kch);  cudaGetSymbolAddress((void**)&Kcl, g_Kcl);
    cudaGetSymbolAddress((void**)&Vch, g_Vch);  cudaGetSymbolAddress((void**)&Vcl, g_Vcl);
    cudaGetSymbolAddress((void**)&Qsh, g_Qsh);  cudaGetSymbolAddress((void**)&Qsl, g_Qsl);
    cudaGetSymbolAddress((void**)&Ksh, g_Ksh);  cudaGetSymbolAddress((void**)&Ksl, g_Ksl);
    cudaGetSymbolAddress((void**)&Vsh, g_Vsh);  cudaGetSymbolAddress((void**)&Vsl, g_Vsl);
    cudaGetSymbolAddress((void**)&P1h, g_P1h);  cudaGetSymbolAddress((void**)&P1l, g_P1l);
    cudaGetSymbolAddress((void**)&P2h, g_P2h);  cudaGetSymbolAddress((void**)&P2l, g_P2l);
    cudaGetSymbolAddress((void**)&P3h, g_P3h);  cudaGetSymbolAddress((void**)&P3l, g_P3l);

    // 1. input/weight splits
    cvt_split_kernel<<<(Bb*Qq*Dd/4 + 255)/256, 256>>>(h_fea, Xhi, Xlo, Bb*Qq*Dd/4);
    WArgs wa;
    wa.W[0] = Wq_custom1; wa.W[1] = Wq_custom; wa.W[2] = Wk_custom; wa.W[3] = Wv_custom;
    wa.W[4] = Wq_charge1; wa.W[5] = Wk_charge; wa.W[6] = Wv_charge; wa.W[7] = W_out;
    cvt_w_kernel<<<8*256*256/256, 256>>>(wa, Wbh, Wbl);

    // 2. merged projections
    HArgs hp;
    hp.Ahi = Xhi; hp.Alo = Xlo; hp.Bh = Wbh; hp.Bl = Wbl;
    hp.Ofp = nullptr; hp.mode = 0;
    hp.Oh[0] = Q1h; hp.Ol[0] = Q1l;
    hp.Oh[1] = Q0h; hp.Ol[1] = Q0l;
    hp.Oh[2] = Kch; hp.Ol[2] = Kcl;
    hp.Oh[3] = Vch; hp.Ol[3] = Vcl;
    hp.Oh[4] = Qsh; hp.Ol[4] = Qsl;
    hp.Oh[5] = Ksh; hp.Ol[5] = Ksl;
    hp.Oh[6] = Vsh; hp.Ol[6] = Vsl;
    hmma_kernel<<<dim3(64, 16), 128>>>(hp);

    // 3. QK^T
    QKArgs qa;
    qa.Q1h = Q1h; qa.Q1l = Q1l; qa.Q0h = Q0h; qa.Q0l = Q0l; qa.Qsh = Qsh; qa.Qsl = Qsl;
    qa.Kch = Kch; qa.Kcl = Kcl; qa.Ksh = Ksh; qa.Ksl = Ksl;
    qa.P1 = P1; qa.P2 = P2; qa.P3 = P3;
    qk_hmma<<<dim3(9, 128), 128>>>(qa);

    // 4. tensor-core fuse MLP + softmax (prefetched inputs)
    fuse_big<<<16*448 + 16*64, 224>>>(P1, P3, aux, P1h, P1l, P3h, P3l, W1, b1, W2, b2);
    fuse_small<<<16*56, 256>>>(P2, aux, P2h, P2l, W1, b1, W2, b2);

    // 5. merged AV -> head splits directly
    AVArgs aa;
    aa.P1h = P1h; aa.P1l = P1l; aa.P2h = P2h; aa.P2l = P2l; aa.P3h = P3h; aa.P3l = P3l;
    aa.Vch = Vch; aa.Vcl = Vcl; aa.Vsh = Vsh; aa.Vsl = Vsl;
    aa.Hhi = Hhi; aa.Hlo = Hlo;
    av_hmma<<<dim3(8, 128), 128>>>(aa);

    // 6. output GEMM
    HArgs ho;
    ho.Ahi = Hhi; ho.Alo = Hlo; ho.Bh = Wbh; ho.Bl = Wbl;
    ho.Ofp = out; ho.mode = 1;
    for (int i = 0; i < 7; i++) { ho.Oh[i] = nullptr; ho.Ol[i] = nullptr; }
    hmma_kernel<<<dim3(64, 4), 128>>>(ho);
}